// round 17
// baseline (speedup 1.0000x reference)
#include <cuda_runtime.h>
#include <cuda_fp16.h>
#include <math_constants.h>
#include <cstdint>

// Problem constants
#define B_   1024
#define NTOK 68
#define C_   768
#define H_   12
#define HD   64
#define M_   (B_ * NTOK)        // 69632
#define K3C  (3 * C_)           // 2304

// Scratch (__device__ globals; allocation-free rule)
__device__ float  g_qkv[(size_t)M_ * K3C];   // QKV output fp32
__device__ __half g_xa [(size_t)M_ * C_];    // x+pe, single fp16
__device__ __half g_whi[(size_t)K3C * C_];   // w_qkv split hi
__device__ __half g_wlo[(size_t)K3C * C_];   // w_qkv split lo
__device__ __half g_phi[(size_t)C_ * C_];    // w_proj split hi
__device__ __half g_plo[(size_t)C_ * C_];    // w_proj split lo
__device__ __half g_aa [(size_t)M_ * C_];    // attention out, single fp16

// ---------------------------------------------------------------------------
// helpers
// ---------------------------------------------------------------------------
static __device__ __forceinline__ uint32_t smem_u32(const void* p) {
    uint32_t a;
    asm("{ .reg .u64 t; cvta.to.shared.u64 t, %1; cvt.u32.u64 %0, t; }"
        : "=r"(a) : "l"(p));
    return a;
}

#define CP16(dst, src) \
    asm volatile("cp.async.cg.shared.global [%0], [%1], 16;" \
                 :: "r"(dst), "l"(src))
#define CP_COMMIT() asm volatile("cp.async.commit_group;" ::: "memory")
#define CP_WAIT1()  asm volatile("cp.async.wait_group 1;"  ::: "memory")

#define LDSM_X4(r, addr) \
    asm volatile("ldmatrix.sync.aligned.m8n8.x4.shared.b16 {%0,%1,%2,%3}, [%4];" \
                 : "=r"((r)[0]), "=r"((r)[1]), "=r"((r)[2]), "=r"((r)[3]) \
                 : "r"(addr))

#define MMA_F16(d, a, b0, b1) \
    asm volatile("mma.sync.aligned.m16n8k16.row.col.f32.f16.f16.f32 " \
                 "{%0,%1,%2,%3}, {%4,%5,%6,%7}, {%8,%9}, {%0,%1,%2,%3};" \
                 : "+f"((d)[0]), "+f"((d)[1]), "+f"((d)[2]), "+f"((d)[3]) \
                 : "r"((a)[0]), "r"((a)[1]), "r"((a)[2]), "r"((a)[3]), \
                   "r"(b0), "r"(b1))

// packed fp32x2 FMA (sm_100-family): d = a*b + d elementwise on fp32 pairs
#define FFMA2(d, a, b) \
    asm("fma.rn.f32x2 %0, %1, %2, %0;" : "+l"(d) : "l"(a), "l"(b))
#define UNPACK2(lo, hi, v) \
    asm("mov.b64 {%0, %1}, %2;" : "=f"(lo), "=f"(hi) : "l"(v))
#define DUP2(d, s) \
    asm("mov.b64 %0, {%1, %1};" : "=l"(d) : "f"(s))

// smem tile: 128 rows x 128 bytes (64 fp16 = one K-chunk of 64), canonical
// SW128 swizzle. 2 stages x 3 tiles (A, Bhi, Blo) x 16KB = 96KB -> 2 CTAs/SM.
static __device__ __forceinline__ uint32_t swf(int row, int c16) {
    return (uint32_t)(row * 128 + (((c16 ^ row) & 7) << 4));
}
#define TILE_ST(s, w) ((s) * 49152 + (w) * 16384)
#define GEMM_SMEM 98304
#define GEMM_GRID 1184

// ---------------------------------------------------------------------------
// split kernels
// ---------------------------------------------------------------------------
__global__ void split_x_pe_f16(const float* __restrict__ x,
                               const float* __restrict__ pe,
                               __half* __restrict__ a)
{
    const size_t i4 = (size_t)blockIdx.x * blockDim.x + threadIdx.x;
    const size_t e  = i4 * 4;
    if (e >= (size_t)M_ * C_) return;
    const int row = (int)(e / C_);
    const int col = (int)(e % C_);
    const int tok = row % NTOK;

    float4 v = *reinterpret_cast<const float4*>(x + e);
    if (tok >= 4) {
        const float4 p = *reinterpret_cast<const float4*>(
            pe + (size_t)(tok + 28) * C_ + col);
        v.x += p.x; v.y += p.y; v.z += p.z; v.w += p.w;
    }
    __half2* ap = reinterpret_cast<__half2*>(a + e);
    ap[0] = __half2(__float2half_rn(v.x), __float2half_rn(v.y));
    ap[1] = __half2(__float2half_rn(v.z), __float2half_rn(v.w));
}

__global__ void split_w_f16(const float* __restrict__ w,
                            __half* __restrict__ hi,
                            __half* __restrict__ lo,
                            size_t n_elem)
{
    const size_t i4 = (size_t)blockIdx.x * blockDim.x + threadIdx.x;
    const size_t e  = i4 * 4;
    if (e >= n_elem) return;
    const float4 v = *reinterpret_cast<const float4*>(w + e);
    __half h0 = __float2half_rn(v.x), l0 = __float2half_rn(v.x - __half2float(h0));
    __half h1 = __float2half_rn(v.y), l1 = __float2half_rn(v.y - __half2float(h1));
    __half h2 = __float2half_rn(v.z), l2 = __float2half_rn(v.z - __half2float(h2));
    __half h3 = __float2half_rn(v.w), l3 = __float2half_rn(v.w - __half2float(h3));
    __half2* hp = reinterpret_cast<__half2*>(hi + e);
    __half2* lp = reinterpret_cast<__half2*>(lo + e);
    hp[0] = __half2(h0, h1); hp[1] = __half2(h2, h3);
    lp[0] = __half2(l0, l1); lp[1] = __half2(l2, l3);
}

// ---------------------------------------------------------------------------
// Persistent GEMM: C = A·W^T + bias, D = A*Bhi + A*Blo (fp16 mma, fp32 acc).
// CTA 128x128, 4 warps (2m x 2n), warp tile 64x64 (A dup x2, B dup x2:
// 25% less LDSM crossbar traffic than 64x32/8-warp), K-chunk 64 (4 quarter
// rounds), 2-stage cp.async ring, 2 CTAs/SM, persistent grid-stride tiles.
// ---------------------------------------------------------------------------
__global__ __launch_bounds__(128, 2)
void gemm_f16x2_kernel(const __half* __restrict__ A,
                       const __half* __restrict__ Bhi,
                       const __half* __restrict__ Blo,
                       const float* __restrict__ bias,
                       float* __restrict__ Cout,
                       int N, int K, int NT, int TT)
{
    extern __shared__ char smem[];
    const uint32_t sb = smem_u32(smem);

    const int tid  = threadIdx.x;   // 0..127
    const int wid  = tid >> 5;      // 0..3
    const int lane = tid & 31;
    const int wm   = wid & 1;       // 0..1
    const int wn   = wid >> 1;      // 0..1

    // ---- cp.async geometry: one 128B row per thread per tile ----
    const int r0 = tid;

#define TILE_OFFSETS(lt_, ao_, bo_)                                   \
    do {                                                              \
        const int cN_ = (lt_) % NT, cM_ = (lt_) / NT;                 \
        ao_ = (size_t)(cM_ * 128 + r0) * K;                           \
        bo_ = (size_t)(cN_ * 128 + r0) * K;                           \
    } while (0)

#define LOAD_STAGE(s, ao_, bo_, k0)                                          \
    do {                                                                      \
        _Pragma("unroll")                                                     \
        for (int i = 0; i < 8; i++) {                                         \
            const uint32_t d = swf(r0, i);                                    \
            const size_t   g = (ao_) + (k0) + i * 8;                          \
            const size_t   gb = (bo_) + (k0) + i * 8;                         \
            CP16(sb + TILE_ST(s, 0) + d, A   + g);                            \
            CP16(sb + TILE_ST(s, 1) + d, Bhi + gb);                           \
            CP16(sb + TILE_ST(s, 2) + d, Blo + gb);                           \
        }                                                                     \
    } while (0)

    // per-warp ldmatrix base rows
    const int arow = wm * 64 + (lane & 15);   // + mf*16
    const int brow = wn * 64 + (lane & 15);   // + bf*16
    const int chi  = lane >> 4;               // 16B sub-chunk within quarter

#define FRAG_LOAD(st, t)                                                     \
    do {                                                                      \
        _Pragma("unroll")                                                     \
        for (int mf = 0; mf < 4; mf++) {                                      \
            const uint32_t ao_ = swf(arow + mf * 16, 2 * (t) + chi);          \
            LDSM_X4(Aa[mf], sb + TILE_ST(st, 0) + ao_);                       \
        }                                                                     \
        _Pragma("unroll")                                                     \
        for (int bf = 0; bf < 4; bf++) {                                      \
            const uint32_t bo_ = swf(brow + bf * 16, 2 * (t) + chi);          \
            LDSM_X4(Bh[bf], sb + TILE_ST(st, 1) + bo_);                       \
            LDSM_X4(Bl[bf], sb + TILE_ST(st, 2) + bo_);                       \
        }                                                                     \
    } while (0)

// term-major: 2 passes of 32 independent-accumulator MMAs each
#define MMA_ALL()                                                            \
    do {                                                                      \
        _Pragma("unroll")                                                     \
        for (int mf = 0; mf < 4; mf++) {                                      \
            _Pragma("unroll")                                                 \
            for (int nf = 0; nf < 8; nf++) {                                  \
                const int g = nf >> 1, h = nf & 1;                            \
                MMA_F16(acc[mf][nf], Aa[mf], Bh[g][h], Bh[g][h + 2]);         \
            }                                                                 \
        }                                                                     \
        _Pragma("unroll")                                                     \
        for (int mf = 0; mf < 4; mf++) {                                      \
            _Pragma("unroll")                                                 \
            for (int nf = 0; nf < 8; nf++) {                                  \
                const int g = nf >> 1, h = nf & 1;                            \
                MMA_F16(acc[mf][nf], Aa[mf], Bl[g][h], Bl[g][h + 2]);         \
            }                                                                 \
        }                                                                     \
    } while (0)

    float acc[4][8][4];
#pragma unroll
    for (int i = 0; i < 4; i++)
#pragma unroll
        for (int j = 0; j < 8; j++)
#pragma unroll
            for (int r = 0; r < 4; r++) acc[i][j][r] = 0.0f;

    const int NC = K >> 6;   // 12 (even)

    uint32_t Aa[4][4], Bh[4][4], Bl[4][4];

    int lt = blockIdx.x;
    if (lt >= TT) return;

    size_t ao, bo;
    TILE_OFFSETS(lt, ao, bo);

    // ---- prologue: both stages in flight ----
    LOAD_STAGE(0, ao, bo, 0);    CP_COMMIT();
    LOAD_STAGE(1, ao, bo, 64);   CP_COMMIT();
    CP_WAIT1();
    __syncthreads();

    for (;;) {
        for (int kc = 0; kc < NC; kc++) {
            const int cur = kc & 1;

            FRAG_LOAD(cur, 0); MMA_ALL();
            FRAG_LOAD(cur, 1); MMA_ALL();
            FRAG_LOAD(cur, 2); MMA_ALL();
            FRAG_LOAD(cur, 3); MMA_ALL();

            __syncthreads();   // all warps done reading slot cur

            const int rc = kc + 2;
            if (rc < NC) {
                LOAD_STAGE(cur, ao, bo, rc * 64);
            } else {
                const int ltn = lt + (int)gridDim.x;
                if (ltn < TT) {
                    size_t nao, nbo;
                    TILE_OFFSETS(ltn, nao, nbo);
                    LOAD_STAGE(cur, nao, nbo, (rc - NC) * 64);
                }
            }
            CP_COMMIT();

            CP_WAIT1();        // chunk kc+1 complete
            __syncthreads();
        }

        // ---- epilogue for tile lt (next tile's loads in flight) ----
        {
            const int cN = lt % NT, cM = lt / NT;
#pragma unroll
            for (int mf = 0; mf < 4; mf++) {
                const int row = cM * 128 + wm * 64 + mf * 16 + (lane >> 2);
#pragma unroll
                for (int nf = 0; nf < 8; nf++) {
                    const int col = cN * 128 + wn * 64 + nf * 8 + (lane & 3) * 2;
                    const float2 bb = *reinterpret_cast<const float2*>(bias + col);
                    float2 o0, o1;
                    o0.x = acc[mf][nf][0] + bb.x;  o0.y = acc[mf][nf][1] + bb.y;
                    o1.x = acc[mf][nf][2] + bb.x;  o1.y = acc[mf][nf][3] + bb.y;
                    *reinterpret_cast<float2*>(Cout + (size_t)row * N + col) = o0;
                    *reinterpret_cast<float2*>(Cout + (size_t)(row + 8) * N + col) = o1;
                }
            }
        }
#pragma unroll
        for (int i = 0; i < 4; i++)
#pragma unroll
            for (int j = 0; j < 8; j++)
#pragma unroll
                for (int r = 0; r < 4; r++) acc[i][j][r] = 0.0f;

        lt += (int)gridDim.x;
        if (lt >= TT) break;
        TILE_OFFSETS(lt, ao, bo);
        // slot 0 holds new tile's chunk 0, slot 1 chunk 1 (both waited+synced)
    }
#undef TILE_OFFSETS
#undef LOAD_STAGE
#undef FRAG_LOAD
#undef MMA_ALL
}

// ---------------------------------------------------------------------------
// Attention (FFMA2, bank-swizzled K) — unchanged from round 16.
// ---------------------------------------------------------------------------
typedef unsigned long long u64;

__global__ __launch_bounds__(256)
void attention_kernel(const float* __restrict__ qkv,
                      const float* __restrict__ mask,
                      __half* __restrict__ oa)
{
    __shared__ u64   skp[NTOK][33];           // col swizzled by row bit 4
    __shared__ float sv2[NTOK][HD];
    __shared__ float sq[8][4][HD];
    __shared__ float sp[8][4][NTOK];

    const int bh = blockIdx.x;
    const int b  = bh / H_;
    const int h  = bh % H_;
    const int tid  = threadIdx.x;
    const int warp = tid >> 5;
    const int lane = tid & 31;

    const size_t base = (size_t)b * NTOK * K3C + (size_t)h * HD;
    for (int idx = tid; idx < NTOK * (HD / 2); idx += 256) {
        const int j = idx / (HD / 2), l = idx % (HD / 2);
        const float2 kv = *reinterpret_cast<const float2*>(
            qkv + base + (size_t)j * K3C + C_ + 2 * l);
        u64 pk;
        asm("mov.b64 %0, {%1, %2};" : "=l"(pk) : "f"(kv.x), "f"(kv.y));
        skp[j][l ^ ((j >> 4) & 1)] = pk;
        const float2 v = *reinterpret_cast<const float2*>(
            qkv + base + (size_t)j * K3C + 2 * C_ + 2 * l);
        *reinterpret_cast<float2*>(&sv2[j][2 * l]) = v;
    }
    __syncthreads();

    const float scale = 0.125f;
    const float* mrow_base = mask + (size_t)b * NTOK * NTOK;
    const int j0 = lane;
    const int j1 = lane + 32;
    const int j2 = (lane < 4) ? lane + 64 : 67;

    const int sw0 = (j0 >> 4) & 1;
    const int sw1 = (j1 >> 4) & 1;
    const int sw2 = (j2 >> 4) & 1;

    for (int g = warp; g < 17; g += 8) {
        const int row0 = g * 4;

#pragma unroll
        for (int r = 0; r < 4; r++) {
            sq[warp][r][lane]      = qkv[base + (size_t)(row0 + r) * K3C + lane]      * scale;
            sq[warp][r][lane + 32] = qkv[base + (size_t)(row0 + r) * K3C + lane + 32] * scale;
        }
        __syncwarp();

        u64 s2[4][3];
#pragma unroll
        for (int r = 0; r < 4; r++)
            s2[r][0] = s2[r][1] = s2[r][2] = 0ull;

        const u64* q0 = reinterpret_cast<const u64*>(sq[warp][0]);
        const u64* q1 = reinterpret_cast<const u64*>(sq[warp][1]);
        const u64* q2p = reinterpret_cast<const u64*>(sq[warp][2]);
        const u64* q3 = reinterpret_cast<const u64*>(sq[warp][3]);

#pragma unroll
        for (int dp = 0; dp < HD / 2; dp++) {
            const u64 k0 = skp[j0][dp ^ sw0];
            const u64 k1 = skp[j1][dp ^ sw1];
            const u64 k2 = skp[j2][dp ^ sw2];
            const u64 qq0 = q0[dp], qq1 = q1[dp], qq2 = q2p[dp], qq3 = q3[dp];
            FFMA2(s2[0][0], qq0, k0); FFMA2(s2[0][1], qq0, k1); FFMA2(s2[0][2], qq0, k2);
            FFMA2(s2[1][0], qq1, k0); FFMA2(s2[1][1], qq1, k1); FFMA2(s2[1][2], qq1, k2);
            FFMA2(s2[2][0], qq2, k0); FFMA2(s2[2][1], qq2, k1); FFMA2(s2[2][2], qq2, k2);
            FFMA2(s2[3][0], qq3, k0); FFMA2(s2[3][1], qq3, k1); FFMA2(s2[3][2], qq3, k2);
        }

        float s[4][3];
#pragma unroll
        for (int r = 0; r < 4; r++) {
#pragma unroll
            for (int t = 0; t < 3; t++) {
                float lo, hi;
                UNPACK2(lo, hi, s2[r][t]);
                s[r][t] = lo + hi;
            }
            const float* mrow = mrow_base + (size_t)(row0 + r) * NTOK;
            s[r][0] += mrow[j0];
            s[r][1] += mrow[j1];
            s[r][2] = (lane < 4) ? (s[r][2] + mrow[j2]) : -CUDART_INF_F;
        }

#pragma unroll
        for (int r = 0; r < 4; r++) {
            float mx = fmaxf(fmaxf(s[r][0], s[r][1]), s[r][2]);
#pragma unroll
            for (int off = 16; off > 0; off >>= 1)
                mx = fmaxf(mx, __shfl_xor_sync(0xffffffffu, mx, off));

            const float e0 = __expf(s[r][0] - mx);
            const float e1 = __expf(s[r][1] - mx);
            const float e2 = (lane < 4) ? __expf(s[r][2] - mx) : 0.0f;
            float sum = e0 + e1 + e2;
#pragma unroll
            for (int off = 16; off > 0; off >>= 1)
                sum += __shfl_xor_sync(0xffffffffu, sum, off);
            const float inv = 1.0f / sum;

            sp[warp][r][j0] = e0 * inv;
            sp[warp][r][j1] = e1 * inv;
            if (lane < 4) sp[warp][r][j2] = e2 * inv;
        }
        __syncwarp();

        u64 o2[4];
#pragma unroll
        for (int r = 0; r < 4; r++) o2[r] = 0ull;

#pragma unroll
        for (int j = 0; j < NTOK; j++) {
            const u64 vv = *reinterpret_cast<const u64*>(&sv2[j][2 * lane]);
            u64 pp0, pp1, pp2, pp3;
            DUP2(pp0, sp[warp][0][j]);
            DUP2(pp1, sp[warp][1][j]);
            DUP2(pp2, sp[warp][2][j]);
            DUP2(pp3, sp[warp][3][j]);
            FFMA2(o2[0], vv, pp0);
            FFMA2(o2[1], vv, pp1);
            FFMA2(o2[2], vv, pp2);
            FFMA2(o2[3], vv, pp3);
        }

#pragma unroll
        for (int r = 0; r < 4; r++) {
            float lo, hi;
            UNPACK2(lo, hi, o2[r]);
            const size_t obase = ((size_t)b * NTOK + row0 + r) * C_ + (size_t)h * HD;
            *reinterpret_cast<__half2*>(oa + obase + 2 * lane) =
                __half2(__float2half_rn(lo), __float2half_rn(hi));
        }
        __syncwarp();
    }
}

// ---------------------------------------------------------------------------
extern "C" void kernel_launch(void* const* d_in, const int* in_sizes, int n_in,
                              void* d_out, int out_size)
{
    const float* x      = (const float*)d_in[0];
    const float* pe     = (const float*)d_in[1];
    const float* mask   = (const float*)d_in[2];
    const float* w_qkv  = (const float*)d_in[3];
    const float* b_qkv  = (const float*)d_in[4];
    const float* w_proj = (const float*)d_in[5];
    const float* b_proj = (const float*)d_in[6];
    float* out = (float*)d_out;

    float* qkv_buf; cudaGetSymbolAddress((void**)&qkv_buf, g_qkv);
    __half *xa, *whi, *wlo, *phi, *plo, *aa;
    cudaGetSymbolAddress((void**)&xa,  g_xa);
    cudaGetSymbolAddress((void**)&whi, g_whi);
    cudaGetSymbolAddress((void**)&wlo, g_wlo);
    cudaGetSymbolAddress((void**)&phi, g_phi);
    cudaGetSymbolAddress((void**)&plo, g_plo);
    cudaGetSymbolAddress((void**)&aa,  g_aa);

    cudaFuncSetAttribute(gemm_f16x2_kernel,
                         cudaFuncAttributeMaxDynamicSharedMemorySize, GEMM_SMEM);

    // 0) precompute fp16 activations + split weights
    {
        const size_t nx = (size_t)M_ * C_ / 4;
        split_x_pe_f16<<<(unsigned)((nx + 255) / 256), 256>>>(x, pe, xa);
        const size_t nw = (size_t)K3C * C_;
        split_w_f16<<<(unsigned)((nw / 4 + 255) / 256), 256>>>(w_qkv, whi, wlo, nw);
        const size_t np = (size_t)C_ * C_;
        split_w_f16<<<(unsigned)((np / 4 + 255) / 256), 256>>>(w_proj, phi, plo, np);
    }

    // 1) QKV projection: (M x 768) @ (768 x 2304)^T + bias -> g_qkv (fp32)
    {
        const int NT = K3C / 128;           // 18
        const int TT = (M_ / 128) * NT;     // 9792
        gemm_f16x2_kernel<<<GEMM_GRID, 128, GEMM_SMEM>>>(
            xa, whi, wlo, b_qkv, qkv_buf, K3C, C_, NT, TT);
    }

    // 2) Attention -> fp16 output
    attention_kernel<<<B_ * H_, 256>>>(qkv_buf, mask, aa);

    // 3) Output projection -> d_out
    {
        const int NT = C_ / 128;            // 6
        const int TT = (M_ / 128) * NT;     // 4080
        gemm_f16x2_kernel<<<GEMM_GRID, 128, GEMM_SMEM>>>(
            aa, phi, plo, b_proj, out, C_, C_, NT, TT);
    }
}